// round 1
// baseline (speedup 1.0000x reference)
#include <cuda_runtime.h>
#include <math.h>

#define SEQ 2048
#define DM 1024
#define NH 16
#define DK 64

// Scratch (static device globals — no runtime allocation allowed)
__device__ float g_Q[SEQ * DM];
__device__ float g_K[SEQ * DM];
__device__ float g_V[SEQ * DM];
__device__ float g_BR[SEQ * DM];

// ---------------------------------------------------------------------------
// Kernel 1: batched projection GEMM.  C[n][h*64+k] = sum_d X[n][d] * W[d][h*64+k]
// z = 0:Q, 1:K, 2:V, 3:b_rotate.  Tile 64x64, 256 threads, 4x4 micro-tile, BK=16.
// ---------------------------------------------------------------------------
__global__ __launch_bounds__(256) void proj_gemm(
    const float* __restrict__ query, const float* __restrict__ key,
    const float* __restrict__ value, const float* __restrict__ bemb,
    const float* __restrict__ LL, const float* __restrict__ bproj)
{
    int z = blockIdx.z;
    const float* X = (z == 0) ? query : (z == 1) ? key : (z == 2) ? value : bemb;
    const float* W = (z < 3) ? (LL + (size_t)z * DM * DM) : bproj;
    float* C = (z == 0) ? g_Q : (z == 1) ? g_K : (z == 2) ? g_V : g_BR;

    __shared__ float As[16][64];   // [k][m] transposed
    __shared__ float Bs[16][64];   // [k][n]

    int tid = threadIdx.x;
    int tx = tid & 15, ty = tid >> 4;
    int m0 = blockIdx.y * 64, n0 = blockIdx.x * 64;

    float acc[4][4] = {};

    int arow = tid >> 2, ac4 = tid & 3;    // A tile load mapping (64 rows x 4 float4)
    int brow = tid >> 4, bc4 = tid & 15;   // B tile load mapping (16 rows x 16 float4)

    for (int k0 = 0; k0 < DM; k0 += 16) {
        float4 av = *(const float4*)(X + (size_t)(m0 + arow) * DM + k0 + ac4 * 4);
        float4 bv = *(const float4*)(W + (size_t)(k0 + brow) * DM + n0 + bc4 * 4);
        As[ac4 * 4 + 0][arow] = av.x;
        As[ac4 * 4 + 1][arow] = av.y;
        As[ac4 * 4 + 2][arow] = av.z;
        As[ac4 * 4 + 3][arow] = av.w;
        *(float4*)&Bs[brow][bc4 * 4] = bv;
        __syncthreads();
        #pragma unroll
        for (int kk = 0; kk < 16; kk++) {
            float4 a = *(const float4*)&As[kk][ty * 4];
            float4 b = *(const float4*)&Bs[kk][tx * 4];
            float ar[4] = {a.x, a.y, a.z, a.w};
            float br[4] = {b.x, b.y, b.z, b.w};
            #pragma unroll
            for (int i = 0; i < 4; i++)
                #pragma unroll
                for (int j = 0; j < 4; j++)
                    acc[i][j] += ar[i] * br[j];
        }
        __syncthreads();
    }
    #pragma unroll
    for (int i = 0; i < 4; i++) {
        float4 v = make_float4(acc[i][0], acc[i][1], acc[i][2], acc[i][3]);
        *(float4*)(C + (size_t)(m0 + ty * 4 + i) * DM + n0 + tx * 4) = v;
    }
}

// ---------------------------------------------------------------------------
// Kernel 2: RoPE (in place on g_Q, g_K) with b_rotate elementwise scaling.
// One thread per (n, h, pair i).
// ---------------------------------------------------------------------------
__global__ void rope_kernel()
{
    int t = blockIdx.x * blockDim.x + threadIdx.x;   // 0 .. SEQ*NH*32-1
    int i = t & 31;
    int h = (t >> 5) & 15;
    int n = t >> 9;
    if (n >= SEQ) return;

    // inv_freq = 10000^{-i/32}; compute in double, round to fp32 (matches jnp fp32 value)
    float inv = (float)exp(-(double)i * (9.210340371976184 / 32.0)); // ln(10000)/32
    float ang = (float)n * inv;
    float sa, ca;
    sincosf(ang, &sa, &ca);

    size_t base = (size_t)n * DM + h * DK + 2 * i;
    float br0 = g_BR[base], br1 = g_BR[base + 1];

    float q0 = g_Q[base], q1 = g_Q[base + 1];
    g_Q[base]     = (q0 * ca - q1 * sa) * br0;
    g_Q[base + 1] = (q0 * sa + q1 * ca) * br1;

    float k0 = g_K[base], k1 = g_K[base + 1];
    g_K[base]     = (k0 * ca - k1 * sa) * br0;
    g_K[base + 1] = (k0 * sa + k1 * ca) * br1;
}

// ---------------------------------------------------------------------------
// Kernel 3: flash attention (fp32, online softmax).
// Grid (SEQ/128, NH); 128 threads; thread owns one q-row. BN=16 K/V tile in smem.
// All smem reads in the hot loops are warp-uniform (broadcast, conflict-free).
// Mask read as 4-byte words, nonzero test (works for int32 and float32 encodings).
// ---------------------------------------------------------------------------
__global__ __launch_bounds__(128, 2) void attn_kernel(
    const unsigned int* __restrict__ mask, float* __restrict__ out)
{
    int h = blockIdx.y;
    int r = blockIdx.x * 128 + threadIdx.x;

    __shared__ float ks[16][64];
    __shared__ float vs[16][64];
    __shared__ unsigned char mk[SEQ];

    for (int i = threadIdx.x; i < SEQ; i += 128)
        mk[i] = (mask[i] != 0u) ? 1 : 0;

    float q[64];
    {
        const float4* qp = (const float4*)(g_Q + (size_t)r * DM + h * DK);
        #pragma unroll
        for (int i = 0; i < 16; i++) {
            float4 v = qp[i];
            q[4 * i] = v.x; q[4 * i + 1] = v.y; q[4 * i + 2] = v.z; q[4 * i + 3] = v.w;
        }
    }
    bool mr = (mask[r] != 0u);

    float o[64];
    #pragma unroll
    for (int d = 0; d < 64; d++) o[d] = 0.f;
    float m = -INFINITY, l = 0.f;
    __syncthreads();

    const float4* Kb = (const float4*)g_K;
    const float4* Vb = (const float4*)g_V;
    int t = threadIdx.x;

    for (int k0 = 0; k0 < SEQ; k0 += 16) {
        // Cooperative load of K/V tiles: 16 rows x 64 floats = 256 float4 each
        #pragma unroll
        for (int u = 0; u < 2; u++) {
            int f = t + u * 128;          // 0..255
            int j = f >> 4, d4 = f & 15;
            size_t gi = ((size_t)(k0 + j) * DM + h * DK) / 4 + d4;
            ((float4*)ks)[f] = Kb[gi];
            ((float4*)vs)[f] = Vb[gi];
        }
        __syncthreads();

        // scores: 16 independent accumulator chains
        float s[16];
        #pragma unroll
        for (int j = 0; j < 16; j++) s[j] = 0.f;
        #pragma unroll
        for (int d4 = 0; d4 < 16; d4++) {
            float qa = q[4 * d4 + 0], qb = q[4 * d4 + 1];
            float qc = q[4 * d4 + 2], qd = q[4 * d4 + 3];
            #pragma unroll
            for (int j = 0; j < 16; j++) {
                float4 kv = *(const float4*)&ks[j][d4 * 4];   // warp-broadcast
                s[j] += qa * kv.x + qb * kv.y + qc * kv.z + qd * kv.w;
            }
        }

        // mask + online softmax update
        float tm = -INFINITY;
        #pragma unroll
        for (int j = 0; j < 16; j++) {
            bool ok = mr && mk[k0 + j];
            s[j] = ok ? s[j] * 0.125f : -1e30f;
            tm = fmaxf(tm, s[j]);
        }
        float mnew = fmaxf(m, tm);
        float scale = __expf(m - mnew);   // m=-inf first iter -> 0
        float ps = 0.f;
        #pragma unroll
        for (int j = 0; j < 16; j++) { s[j] = __expf(s[j] - mnew); ps += s[j]; }
        l = l * scale + ps;
        #pragma unroll
        for (int d = 0; d < 64; d++) o[d] *= scale;

        // o += p @ V
        #pragma unroll
        for (int j = 0; j < 16; j++) {
            float pj = s[j];
            #pragma unroll
            for (int d4 = 0; d4 < 16; d4++) {
                float4 vv = *(const float4*)&vs[j][d4 * 4];   // warp-broadcast
                o[4 * d4 + 0] += pj * vv.x;
                o[4 * d4 + 1] += pj * vv.y;
                o[4 * d4 + 2] += pj * vv.z;
                o[4 * d4 + 3] += pj * vv.w;
            }
        }
        m = mnew;
        __syncthreads();
    }

    float invl = 1.f / l;
    float4* op = (float4*)(out + (size_t)r * DM + h * DK);
    #pragma unroll
    for (int d4 = 0; d4 < 16; d4++) {
        float4 v = make_float4(o[4 * d4] * invl, o[4 * d4 + 1] * invl,
                               o[4 * d4 + 2] * invl, o[4 * d4 + 3] * invl);
        op[d4] = v;
    }
}

// ---------------------------------------------------------------------------
extern "C" void kernel_launch(void* const* d_in, const int* in_sizes, int n_in,
                              void* d_out, int out_size)
{
    const float* query = (const float*)d_in[0];
    const float* key   = (const float*)d_in[1];
    const float* value = (const float*)d_in[2];
    const float* bemb  = (const float*)d_in[3];
    const unsigned int* mask = (const unsigned int*)d_in[4];
    const float* LL    = (const float*)d_in[5];
    const float* bproj = (const float*)d_in[6];
    float* out = (float*)d_out;

    dim3 gg(DM / 64, SEQ / 64, 4);
    proj_gemm<<<gg, 256>>>(query, key, value, bemb, LL, bproj);

    rope_kernel<<<(SEQ * NH * 32) / 256, 256>>>();

    dim3 ga(SEQ / 128, NH);
    attn_kernel<<<ga, 128>>>(mask, out);
}